// round 17
// baseline (speedup 1.0000x reference)
#include <cuda_runtime.h>
#include <cuda_fp16.h>
#include <math.h>

#define Tsz 512
#define FS 64
#define FC 32
#define H 256
#define LN_EPS 1e-5f

// ============================================================================
// Weight storage: pre-swizzled mma.m16n8k16 A-fragments (fp16).
// idx = kt*512 + w*32 + lane (uint4 = full 8-half a-frag).
// ============================================================================
__device__ uint4 gA_p0a[4 * 512];    // Win0 seq part  (K=64)
__device__ uint4 gA_p0b[4 * 512];    // Wg0  seq part
__device__ uint4 gA_c0a[2 * 512];    // Win0 ctx part  (K=32)
__device__ uint4 gA_c0b[2 * 512];    // Wg0  ctx part
__device__ uint4 gA_h0a[16 * 512];   // Wg0  h part    (K=256)
__device__ uint4 gA_h0b[16 * 512];   // Wrec0
__device__ uint4 gA_x1a[16 * 512];   // Win1
__device__ uint4 gA_x1b[16 * 512];   // Wg1 x part
__device__ uint4 gA_h1a[16 * 512];   // Wg1 h part
__device__ uint4 gA_h1b[16 * 512];   // Wrec1

__device__ __forceinline__ unsigned pack_h2(float a, float b) {
    __half2 h = __floats2half2_rn(a, b);
    return *reinterpret_cast<unsigned*>(&h);
}

__global__ void setup_kernel(const float* __restrict__ Win0,
                             const float* __restrict__ Wrec0,
                             const float* __restrict__ Wg0,
                             const float* __restrict__ Win1,
                             const float* __restrict__ Wrec1,
                             const float* __restrict__ Wg1) {
    int idx = blockIdx.x * 512 + threadIdx.x;   // 0 .. 55295
    const float* src; int jstr, koff; uint4* dst; int base;
    if      (idx <  2048) { dst = gA_p0a; base = 0;     src = Win0;  jstr = 96;  koff = 0;   }
    else if (idx <  4096) { dst = gA_p0b; base = 2048;  src = Wg0;   jstr = 352; koff = 0;   }
    else if (idx <  5120) { dst = gA_c0a; base = 4096;  src = Win0;  jstr = 96;  koff = 64;  }
    else if (idx <  6144) { dst = gA_c0b; base = 5120;  src = Wg0;   jstr = 352; koff = 64;  }
    else if (idx < 14336) { dst = gA_h0a; base = 6144;  src = Wg0;   jstr = 352; koff = 96;  }
    else if (idx < 22528) { dst = gA_h0b; base = 14336; src = Wrec0; jstr = 256; koff = 0;   }
    else if (idx < 30720) { dst = gA_x1a; base = 22528; src = Win1;  jstr = 256; koff = 0;   }
    else if (idx < 38912) { dst = gA_x1b; base = 30720; src = Wg1;   jstr = 512; koff = 0;   }
    else if (idx < 47104) { dst = gA_h1a; base = 38912; src = Wg1;   jstr = 512; koff = 256; }
    else                  { dst = gA_h1b; base = 47104; src = Wrec1; jstr = 256; koff = 0;   }
    int li = idx - base;
    int lane = li & 31, w = (li >> 5) & 15, kt = li >> 9;
    int r = lane >> 2, c = (lane & 3) * 2;
    int j0 = w * 16 + r, k0 = kt * 16 + c;
    const float* r0 = src + (size_t)j0 * jstr + koff;
    const float* r8 = src + (size_t)(j0 + 8) * jstr + koff;
    uint4 u;
    u.x = pack_h2(r0[k0],     r0[k0 + 1]);
    u.y = pack_h2(r8[k0],     r8[k0 + 1]);
    u.z = pack_h2(r0[k0 + 8], r0[k0 + 9]);
    u.w = pack_h2(r8[k0 + 8], r8[k0 + 9]);
    dst[li] = u;
}

// ============================================================================
// Device helpers
// ============================================================================
__device__ __forceinline__ void mma16816(float c[4], uint4 a, unsigned b0, unsigned b1) {
    asm volatile(
        "mma.sync.aligned.m16n8k16.row.col.f32.f16.f16.f32 "
        "{%0,%1,%2,%3},{%4,%5,%6,%7},{%8,%9},{%0,%1,%2,%3};"
        : "+f"(c[0]), "+f"(c[1]), "+f"(c[2]), "+f"(c[3])
        : "r"(a.x), "r"(a.y), "r"(a.z), "r"(a.w), "r"(b0), "r"(b1));
}

__device__ __forceinline__ float fast_tanh(float x) {
    float xc = fminf(fmaxf(x, -15.f), 15.f);
    float e  = __expf(2.f * xc);
    return __fdividef(e - 1.f, e + 1.f);
}
__device__ __forceinline__ float fast_sigmoid(float x) {
    return __fdividef(1.f, 1.f + __expf(-x));
}

// Preload the kt=0 fragments of both matrices (issued BEFORE a barrier so the
// L2 latency overlaps the barrier wait; addresses are barrier-independent).
__device__ __forceinline__ void preK(const uint4* __restrict__ ga,
                                     const uint4* __restrict__ gb,
                                     int base, uint4& pa, uint4& pb) {
    pa = ga[base];
    pb = gb[base];
}

// Dual-matrix MMA sweep with hi/lo packed B (hi cols 0-3, lo cols 4-7).
// One MMA serves both; post-sweep shfl_xor(2) recombines. All lanes end valid.
template<int NKT, int STR>
__device__ __forceinline__ void sweep2(const uint4* __restrict__ ga,
                                       const uint4* __restrict__ gb,
                                       const __half* __restrict__ B,
                                       int w, int lane,
                                       float c1[4], float c2[4]) {
    const int n  = lane >> 2;
    const int k0 = (lane & 3) * 2;
    const __half* bp = B + n * STR + k0;
    const int base = w * 32 + lane;
#pragma unroll 4
    for (int kt = 0; kt < NKT; kt++) {
        uint4 a1 = ga[kt * 512 + base];
        uint4 a2 = gb[kt * 512 + base];
        unsigned b0 = *(const unsigned*)(bp + kt * 16);
        unsigned b1 = *(const unsigned*)(bp + kt * 16 + 8);
        mma16816(c1, a1, b0, b1);
        mma16816(c2, a2, b0, b1);
    }
#pragma unroll
    for (int i = 0; i < 4; i++) {
        c1[i] += __shfl_xor_sync(0xffffffffu, c1[i], 2);
        c2[i] += __shfl_xor_sync(0xffffffffu, c2[i], 2);
    }
}

// Same, but kt=0 fragments come preloaded (pa/pb, loaded before the barrier).
template<int NKT, int STR>
__device__ __forceinline__ void sweep2p(const uint4* __restrict__ ga,
                                        const uint4* __restrict__ gb,
                                        const __half* __restrict__ B,
                                        int w, int lane,
                                        float c1[4], float c2[4],
                                        uint4 pa, uint4 pb) {
    const int n  = lane >> 2;
    const int k0 = (lane & 3) * 2;
    const __half* bp = B + n * STR + k0;
    const int base = w * 32 + lane;
    {
        unsigned b0 = *(const unsigned*)(bp);
        unsigned b1 = *(const unsigned*)(bp + 8);
        mma16816(c1, pa, b0, b1);
        mma16816(c2, pb, b0, b1);
    }
#pragma unroll 4
    for (int kt = 1; kt < NKT; kt++) {
        uint4 a1 = ga[kt * 512 + base];
        uint4 a2 = gb[kt * 512 + base];
        unsigned b0 = *(const unsigned*)(bp + kt * 16);
        unsigned b1 = *(const unsigned*)(bp + kt * 16 + 8);
        mma16816(c1, a1, b0, b1);
        mma16816(c2, a2, b0, b1);
    }
#pragma unroll
    for (int i = 0; i < 4; i++) {
        c1[i] += __shfl_xor_sync(0xffffffffu, c1[i], 2);
        c2[i] += __shfl_xor_sync(0xffffffffu, c2[i], 2);
    }
}

// Write a C-fragment-layout vector v into a packed hi/lo B array [8][264].
__device__ __forceinline__ void writeB(__half* Bp, int lane, int w, const float v[4]) {
    if ((lane & 3) < 2) {
        int n0 = (lane & 3) * 2;
        int j  = w * 16 + (lane >> 2);
#pragma unroll
        for (int e = 0; e < 4; e++) {
            int n  = n0 + (e & 1);
            int jj = j + (e >> 1) * 8;
            float vv = v[e];
            __half hv = __float2half_rn(vv);
            Bp[n * 264 + jj]       = hv;
            Bp[(n + 4) * 264 + jj] = __float2half_rn(vv - __half2float(hv));
        }
    }
}

struct __align__(16) SmemT {
    __half stA[8][264], stB[8][264];   // stage double-buffers (hi/lo packed)
    __half h0[8][264],  h1[8][264];    // layer states (h0 also = layer-1 input)
    __half xs[8][72];                  // seq features at t (K=64)
    __half cx[8][40];                  // ctx features (K=32)
    float  red[256];
    float  stats[16];
};

// One layer at one timestep: proj + 4 RK4 stages + LayerNorm + tanh.
// Entry: pa/pb hold THIS layer's proj kt0 fragments (preloaded pre-barrier).
// The layer's top __syncthreads lives INSIDE. Exit: pa/pb hold gna/gnb kt0.
template<int NKTP, int STRP>
__device__ __forceinline__ void layer_run(
    const uint4* __restrict__ gpa, const uint4* __restrict__ gpb,
    const __half* __restrict__ x,
    const uint4* __restrict__ gsa, const uint4* __restrict__ gsb,
    __half* __restrict__ hB,
    const uint4* __restrict__ gna, const uint4* __restrict__ gnb,
    SmemT& sm, int tid, int w, int lane, int base,
    const float pinI[4], const float pgI[4],
    const float it0, const float it1,
    const float lg0v, const float lg1v, const float lb0v, const float lb1v,
    float h[4], uint4& pa, uint4& pb) {

    __syncthreads();   // top: x, hB, stage bufs ready (pa/pb already in flight)

    float pin[4], pg[4];
#pragma unroll
    for (int i = 0; i < 4; i++) { pin[i] = pinI[i]; pg[i] = pgI[i]; }
    sweep2p<NKTP, STRP>(gpa, gpb, x, w, lane, pin, pg, pa, pb);

    // stage 0 (B = hB, stable since previous epilogue; no barrier needed)
    float cg[4] = {0.f, 0.f, 0.f, 0.f}, cr[4] = {0.f, 0.f, 0.f, 0.f};
    sweep2<16, 264>(gsa, gsb, hB, w, lane, cg, cr);

    float hs[4], kacc[4];
#pragma unroll
    for (int e = 0; e < 4; e++) {
        float gg = fast_sigmoid(fast_tanh(pg[e] + cg[e]));
        float kb = pin[e] - h[e] * ((e < 2) ? it0 : it1) + gg * cr[e];
        kacc[e] = kb;
        hs[e]   = h[e] + 0.5f * kb;
    }
    writeB(&sm.stA[0][0], lane, w, hs);
    preK(gsa, gsb, base, pa, pb);
    __syncthreads();

    // stage 1
#pragma unroll
    for (int i = 0; i < 4; i++) { cg[i] = 0.f; cr[i] = 0.f; }
    sweep2p<16, 264>(gsa, gsb, &sm.stA[0][0], w, lane, cg, cr, pa, pb);
#pragma unroll
    for (int e = 0; e < 4; e++) {
        float gg = fast_sigmoid(fast_tanh(pg[e] + cg[e]));
        float kb = pin[e] - hs[e] * ((e < 2) ? it0 : it1) + gg * cr[e];
        kacc[e] += 2.f * kb;
        hs[e]    = h[e] + 0.5f * kb;
    }
    writeB(&sm.stB[0][0], lane, w, hs);
    preK(gsa, gsb, base, pa, pb);
    __syncthreads();

    // stage 2
#pragma unroll
    for (int i = 0; i < 4; i++) { cg[i] = 0.f; cr[i] = 0.f; }
    sweep2p<16, 264>(gsa, gsb, &sm.stB[0][0], w, lane, cg, cr, pa, pb);
#pragma unroll
    for (int e = 0; e < 4; e++) {
        float gg = fast_sigmoid(fast_tanh(pg[e] + cg[e]));
        float kb = pin[e] - hs[e] * ((e < 2) ? it0 : it1) + gg * cr[e];
        kacc[e] += 2.f * kb;
        hs[e]    = h[e] + kb;
    }
    writeB(&sm.stA[0][0], lane, w, hs);
    preK(gsa, gsb, base, pa, pb);
    __syncthreads();

    // stage 3
#pragma unroll
    for (int i = 0; i < 4; i++) { cg[i] = 0.f; cr[i] = 0.f; }
    sweep2p<16, 264>(gsa, gsb, &sm.stA[0][0], w, lane, cg, cr, pa, pb);
    float hn[4];
#pragma unroll
    for (int e = 0; e < 4; e++) {
        float gg = fast_sigmoid(fast_tanh(pg[e] + cg[e]));
        float kb = pin[e] - hs[e] * ((e < 2) ? it0 : it1) + gg * cr[e];
        kacc[e] += kb;
        hn[e]    = h[e] + kacc[e] * (1.f / 6.f);
    }
    preK(gna, gnb, base, pa, pb);   // next phase's proj chunk, ahead of LN barriers

    // LayerNorm over j (256) per batch col
    float s0 = hn[0] + hn[2], s1 = hn[1] + hn[3];
    float q0 = hn[0] * hn[0] + hn[2] * hn[2];
    float q1 = hn[1] * hn[1] + hn[3] * hn[3];
#pragma unroll
    for (int off = 4; off <= 16; off <<= 1) {
        s0 += __shfl_xor_sync(0xffffffffu, s0, off);
        s1 += __shfl_xor_sync(0xffffffffu, s1, off);
        q0 += __shfl_xor_sync(0xffffffffu, q0, off);
        q1 += __shfl_xor_sync(0xffffffffu, q1, off);
    }
    if (lane < 4) {
        float* rp = sm.red + (w * 4 + lane) * 4;
        rp[0] = s0; rp[1] = s1; rp[2] = q0; rp[3] = q1;
    }
    __syncthreads();
    if (tid < 16) {
        float tsum = 0.f;
#pragma unroll
        for (int ww = 0; ww < 16; ww++)
            tsum += sm.red[(ww * 4 + (tid >> 2)) * 4 + (tid & 3)];
        sm.stats[tid] = tsum;
    }
    __syncthreads();
    int gq = lane & 3;
    float mu0 = sm.stats[gq * 4 + 0] * (1.f / (float)H);
    float mu1 = sm.stats[gq * 4 + 1] * (1.f / (float)H);
    float rs0 = rsqrtf(sm.stats[gq * 4 + 2] * (1.f / (float)H) - mu0 * mu0 + LN_EPS);
    float rs1 = rsqrtf(sm.stats[gq * 4 + 3] * (1.f / (float)H) - mu1 * mu1 + LN_EPS);
#pragma unroll
    for (int e = 0; e < 4; e++) {
        float mu = (e & 1) ? mu1 : mu0;
        float rs = (e & 1) ? rs1 : rs0;
        float lg = (e < 2) ? lg0v : lg1v;
        float lb = (e < 2) ? lb0v : lb1v;
        h[e] = fast_tanh((hn[e] - mu) * rs * lg + lb);   // clip is a no-op
    }
    writeB(hB, lane, w, h);
    // next phase's top barrier protects hB / stage-buffer reuse
}

__global__ __launch_bounds__(512, 1)
void ltc_main(const float* __restrict__ seq,  const float* __restrict__ ctx,
              const float* __restrict__ tau0, const float* __restrict__ bg0,
              const float* __restrict__ lng0, const float* __restrict__ lnb0,
              const float* __restrict__ tau1, const float* __restrict__ bg1,
              const float* __restrict__ lng1, const float* __restrict__ lnb1,
              const float* __restrict__ cW1,  const float* __restrict__ cb1,
              const float* __restrict__ cW2,  const float* __restrict__ cb2,
              float* __restrict__ out) {
    __shared__ SmemT sm;
    int tid  = threadIdx.x;
    int lane = tid & 31, w = tid >> 5;
    int base = w * 32 + lane;
    int b0   = blockIdx.x * 4;

    for (int i = tid; i < (int)(sizeof(SmemT) / 4); i += 512)
        ((int*)&sm)[i] = 0;

    int r  = lane >> 2;
    int j0 = w * 16 + r, j8 = j0 + 8;

    float it0a = 1.f / (log1pf(expf(tau0[j0])) + 1.f);
    float it0b = 1.f / (log1pf(expf(tau0[j8])) + 1.f);
    float it1a = 1.f / (log1pf(expf(tau1[j0])) + 1.f);
    float it1b = 1.f / (log1pf(expf(tau1[j8])) + 1.f);
    float lg0a = lng0[j0], lg0b = lng0[j8], lb0a = lnb0[j0], lb0b = lnb0[j8];
    float lg1a = lng1[j0], lg1b = lng1[j8], lb1a = lnb1[j0], lb1b = lnb1[j8];
    float bg1a = bg1[j0],  bg1b = bg1[j8];
    float bg0a = bg0[j0],  bg0b = bg0[j8];

    __syncthreads();   // zero done

    // ---- ctx features -> cx (hi rows 0-3, lo rows 4-7) ----
    if (tid < FC) {
#pragma unroll
        for (int n = 0; n < 4; n++) {
            float v = ctx[(size_t)(b0 + n) * FC + tid];
            __half hv = __float2half_rn(v);
            sm.cx[n][tid]     = hv;
            sm.cx[n + 4][tid] = __float2half_rn(v - __half2float(hv));
        }
    }
    __syncthreads();

    // ---- ctx-folded pre-activation fragments (constant over t) ----
    float cwinF[4] = {0.f, 0.f, 0.f, 0.f}, cgF[4] = {0.f, 0.f, 0.f, 0.f};
    sweep2<2, 40>(gA_c0a, gA_c0b, &sm.cx[0][0], w, lane, cwinF, cgF);
    cgF[0] += bg0a; cgF[1] += bg0a; cgF[2] += bg0b; cgF[3] += bg0b;
    // Zero init fragments on lo-lanes so the post-sweep combine counts them once.
    if ((lane & 3) >= 2) {
#pragma unroll
        for (int i = 0; i < 4; i++) { cwinF[i] = 0.f; cgF[i] = 0.f; }
    }
    float m = ((lane & 3) < 2) ? 1.f : 0.f;
    float pin1I[4] = {0.f, 0.f, 0.f, 0.f};
    float pg1I[4]  = {bg1a * m, bg1a * m, bg1b * m, bg1b * m};

    float h0f[4] = {0.f, 0.f, 0.f, 0.f};
    float h1f[4] = {0.f, 0.f, 0.f, 0.f};

    // cold-start the prefetch pipeline: layer-0 proj chunk + seq(t=0)
    uint4 pa, pb;
    preK(gA_p0a, gA_p0b, base, pa, pb);
    float sq[4] = {0.f, 0.f, 0.f, 0.f};
    if (tid < FS) {
#pragma unroll
        for (int n = 0; n < 4; n++)
            sq[n] = seq[(size_t)(b0 + n) * Tsz * FS + tid];
    }

#pragma unroll 1
    for (int t = 0; t < Tsz; t++) {
        // store prefetched seq(t); issue fetch of seq(t+1) (whole timestep to land)
        if (tid < FS) {
#pragma unroll
            for (int n = 0; n < 4; n++) {
                __half hv = __float2half_rn(sq[n]);
                sm.xs[n][tid]     = hv;
                sm.xs[n + 4][tid] = __float2half_rn(sq[n] - __half2float(hv));
            }
            int tn = (t + 1 < Tsz) ? t + 1 : t;
            size_t o = (size_t)tn * FS + tid;
#pragma unroll
            for (int n = 0; n < 4; n++)
                sq[n] = seq[(size_t)(b0 + n) * Tsz * FS + o];
        }

        // ---- layer 0 (top barrier inside; covers xs, h1B, stage bufs) ----
        layer_run<4, 72>(gA_p0a, gA_p0b, &sm.xs[0][0],
                         gA_h0a, gA_h0b, &sm.h0[0][0],
                         gA_x1a, gA_x1b,
                         sm, tid, w, lane, base, cwinF, cgF,
                         it0a, it0b, lg0a, lg0b, lb0a, lb0b, h0f, pa, pb);

        // ---- layer 1 (top barrier inside; covers h0B handoff) ----
        layer_run<16, 264>(gA_x1a, gA_x1b, &sm.h0[0][0],
                           gA_h1a, gA_h1b, &sm.h1[0][0],
                           gA_p0a, gA_p0b,
                           sm, tid, w, lane, base, pin1I, pg1I,
                           it1a, it1b, lg1a, lg1b, lb1a, lb1b, h1f, pa, pb);
    }

    // ---- head: out = relu(h1 @ cW1.T + cb1) @ cW2.T + cb2 ----
    __syncthreads();
    float* xf = (float*)&sm.stA[0][0];   // scratch (stA+stB = 2112 halves)
    if (tid < 256) {
#pragma unroll
        for (int n = 0; n < 4; n++)
            xf[n * 256 + tid] =
                __half2float(sm.h1[n][tid]) + __half2float(sm.h1[n + 4][tid]);
    }
    __syncthreads();

    float p[4] = {0.f, 0.f, 0.f, 0.f};
    if (tid < 128) {
        float acc[4];
        float bb = cb1[tid];
#pragma unroll
        for (int b = 0; b < 4; b++) acc[b] = bb;
#pragma unroll 8
        for (int k = 0; k < H; k++) {
            float wv = cW1[tid * H + k];
            acc[0] += wv * xf[k];
            acc[1] += wv * xf[256 + k];
            acc[2] += wv * xf[512 + k];
            acc[3] += wv * xf[768 + k];
        }
        float w2 = cW2[tid];
#pragma unroll
        for (int b = 0; b < 4; b++) p[b] = fmaxf(acc[b], 0.f) * w2;
    }
#pragma unroll
    for (int off = 16; off > 0; off >>= 1) {
#pragma unroll
        for (int b = 0; b < 4; b++)
            p[b] += __shfl_xor_sync(0xffffffffu, p[b], off);
    }
    if (lane == 0) {
#pragma unroll
        for (int b = 0; b < 4; b++) sm.red[w * 4 + b] = p[b];
    }
    __syncthreads();
    if (tid < 4) {
        float o = 0.f;
#pragma unroll
        for (int ww = 0; ww < 16; ww++) o += sm.red[ww * 4 + tid];
        out[b0 + tid] = o + cb2[0];
    }
}

extern "C" void kernel_launch(void* const* d_in, const int* in_sizes, int n_in,
                              void* d_out, int out_size) {
    const float* seq   = (const float*)d_in[0];
    const float* ctx   = (const float*)d_in[1];
    const float* tau0  = (const float*)d_in[2];
    const float* Win0  = (const float*)d_in[3];
    const float* Wrec0 = (const float*)d_in[4];
    const float* Wg0   = (const float*)d_in[5];
    const float* bg0   = (const float*)d_in[6];
    const float* lng0  = (const float*)d_in[7];
    const float* lnb0  = (const float*)d_in[8];
    const float* tau1  = (const float*)d_in[9];
    const float* Win1  = (const float*)d_in[10];
    const float* Wrec1 = (const float*)d_in[11];
    const float* Wg1   = (const float*)d_in[12];
    const float* bg1   = (const float*)d_in[13];
    const float* lng1  = (const float*)d_in[14];
    const float* lnb1  = (const float*)d_in[15];
    const float* cW1   = (const float*)d_in[16];
    const float* cb1   = (const float*)d_in[17];
    const float* cW2   = (const float*)d_in[18];
    const float* cb2   = (const float*)d_in[19];
    float* out = (float*)d_out;

    setup_kernel<<<108, 512>>>(Win0, Wrec0, Wg0, Win1, Wrec1, Wg1);
    ltc_main<<<128, 512>>>(seq, ctx, tau0, bg0, lng0, lnb0,
                           tau1, bg1, lng1, lnb1,
                           cW1, cb1, cW2, cb2, out);
}